// round 1
// baseline (speedup 1.0000x reference)
#include <cuda_runtime.h>
#include <cstdint>

#define NUSERS 100000
#define NITEMS 50000
#define NNODES 150000
#define DIM 64
#define CH (DIM/4)        // 16 float4 chunks per node
#define EMAX 3200000

// ---- scratch (device globals: allocation-free) ----
__device__ __align__(256) float g_x[NNODES * DIM];
__device__ __align__(256) float g_y[NNODES * DIM];
__device__ __align__(256) float g_acc[NNODES * DIM];
__device__ __align__(256) int   g_deg[NNODES];
__device__ __align__(256) float g_dinv[NNODES];
__device__ __align__(256) float g_vals[EMAX];

// ---------------- degree ----------------
__global__ void k_deg(const int* __restrict__ row, int E, int* __restrict__ deg) {
    int i = blockIdx.x * blockDim.x + threadIdx.x;
    if (i < E) atomicAdd(&deg[row[i]], 1);
}

__global__ void k_dinv(const int* __restrict__ deg, float* __restrict__ dinv) {
    int i = blockIdx.x * blockDim.x + threadIdx.x;
    if (i < NNODES) {
        int d = deg[i];
        dinv[i] = (d > 0) ? rsqrtf((float)d) : 0.0f;
    }
}

__global__ void k_vals(const int* __restrict__ row, const int* __restrict__ col,
                       const float* __restrict__ dinv, float* __restrict__ vals, int E) {
    int i = blockIdx.x * blockDim.x + threadIdx.x;
    if (i < E) vals[i] = dinv[row[i]] * dinv[col[i]];
}

// -------------- init x = concat(user_emb, item_emb); acc = x --------------
__global__ void k_init(const float4* __restrict__ ue, const float4* __restrict__ ie,
                       float4* __restrict__ x, float4* __restrict__ acc) {
    int i = blockIdx.x * blockDim.x + threadIdx.x;
    const int total = NNODES * CH;
    if (i >= total) return;
    float4 v = (i < NUSERS * CH) ? ue[i] : ie[i - NUSERS * CH];
    x[i] = v;
    acc[i] = v;
}

// -------------- edge-parallel SpMM with vector atomics --------------
__global__ void k_spmm(const int* __restrict__ row, const int* __restrict__ col,
                       const float* __restrict__ vals,
                       const float4* __restrict__ x, float4* __restrict__ y, int E) {
    unsigned int i = blockIdx.x * blockDim.x + threadIdx.x;
    unsigned int e = i >> 4;          // edge id
    unsigned int c = i & 15u;         // float4 chunk within 64-dim row
    if (e >= (unsigned int)E) return;
    int r  = row[e];
    int cl = col[e];
    float v = vals[e];
    float4 xv = x[(unsigned int)cl * CH + c];
    float4 contrib = make_float4(v * xv.x, v * xv.y, v * xv.z, v * xv.w);
#if __CUDA_ARCH__ >= 900
    atomicAdd(&y[(unsigned int)r * CH + c], contrib);
#else
    float* p = (float*)&y[(unsigned int)r * CH + c];
    atomicAdd(p + 0, contrib.x);
    atomicAdd(p + 1, contrib.y);
    atomicAdd(p + 2, contrib.z);
    atomicAdd(p + 3, contrib.w);
#endif
}

// -------------- acc += y --------------
__global__ void k_accadd(float4* __restrict__ acc, const float4* __restrict__ y) {
    int i = blockIdx.x * blockDim.x + threadIdx.x;
    if (i < NNODES * CH) {
        float4 a = acc[i];
        float4 b = y[i];
        a.x += b.x; a.y += b.y; a.z += b.z; a.w += b.w;
        acc[i] = a;
    }
}

// -------------- scores: one warp per (user, item) pair --------------
__global__ void k_score(const float* __restrict__ acc,
                        const int* __restrict__ uidx, const int* __restrict__ iidx,
                        float* __restrict__ out, int B) {
    int gtid = blockIdx.x * blockDim.x + threadIdx.x;
    int w = gtid >> 5;
    int lane = gtid & 31;
    if (w >= B) return;
    const float2* a = (const float2*)(acc + (size_t)uidx[w] * DIM);
    const float2* b = (const float2*)(acc + (size_t)(NUSERS + iidx[w]) * DIM);
    float2 av = a[lane];
    float2 bv = b[lane];
    float s = av.x * bv.x + av.y * bv.y;
    #pragma unroll
    for (int o = 16; o > 0; o >>= 1) s += __shfl_xor_sync(0xFFFFFFFFu, s, o);
    if (lane == 0) out[w] = s * 0.0625f;   // (1/4)^2 folded into the dot
}

extern "C" void kernel_launch(void* const* d_in, const int* in_sizes, int n_in,
                              void* d_out, int out_size) {
    const float* ue   = (const float*)d_in[0];
    const float* ie   = (const float*)d_in[1];
    const int*   row  = (const int*)d_in[2];
    const int*   col  = (const int*)d_in[3];
    const int*   uidx = (const int*)d_in[4];
    const int*   iidx = (const int*)d_in[5];
    const int E = in_sizes[2];
    const int B = in_sizes[4];

    float *x, *y, *acc, *dinv, *vals;
    int* deg;
    cudaGetSymbolAddress((void**)&x,    g_x);
    cudaGetSymbolAddress((void**)&y,    g_y);
    cudaGetSymbolAddress((void**)&acc,  g_acc);
    cudaGetSymbolAddress((void**)&deg,  g_deg);
    cudaGetSymbolAddress((void**)&dinv, g_dinv);
    cudaGetSymbolAddress((void**)&vals, g_vals);

    const int TB = 256;

    // degree + normalization values
    cudaMemsetAsync(deg, 0, NNODES * sizeof(int));
    k_deg<<<(E + TB - 1) / TB, TB>>>(row, E, deg);
    k_dinv<<<(NNODES + TB - 1) / TB, TB>>>(deg, dinv);
    k_vals<<<(E + TB - 1) / TB, TB>>>(row, col, dinv, vals, E);

    // x = concat(embeddings); acc = x
    k_init<<<(NNODES * CH + TB - 1) / TB, TB>>>((const float4*)ue, (const float4*)ie,
                                                (float4*)x, (float4*)acc);

    // 3 propagation layers, ping-pong x <-> y
    float* bufs[2] = { x, y };
    const long long spmm_threads = (long long)E * CH;
    const int spmm_blocks = (int)((spmm_threads + TB - 1) / TB);
    for (int l = 0; l < 3; ++l) {
        float* in  = bufs[l & 1];
        float* outb = bufs[(l + 1) & 1];
        cudaMemsetAsync(outb, 0, (size_t)NNODES * DIM * sizeof(float));
        k_spmm<<<spmm_blocks, TB>>>(row, col, vals, (const float4*)in, (float4*)outb, E);
        k_accadd<<<(NNODES * CH + TB - 1) / TB, TB>>>((float4*)acc, (const float4*)outb);
    }

    // scores
    k_score<<<(B * 32 + TB - 1) / TB, TB>>>(acc, uidx, iidx, (float*)d_out, B);
}

// round 2
// speedup vs baseline: 2.1456x; 2.1456x over previous
#include <cuda_runtime.h>
#include <cstdint>

#define NUSERS 100000
#define NITEMS 50000
#define NNODES 150000
#define DIM 64
#define EMAX 3200000
#define SCANB 1024
#define NSCANBLK ((NNODES + SCANB - 1) / SCANB)   // 147

// ---- scratch (device globals: allocation-free) ----
__device__ __align__(256) float g_z0[NNODES * DIM];
__device__ __align__(256) float g_z1[NNODES * DIM];
__device__ __align__(256) float g_acc[NNODES * DIM];
__device__ __align__(256) int   g_deg[NNODES];
__device__ __align__(256) float g_dinv[NNODES];
__device__ __align__(256) int   g_rowptr[NNODES + 1];
__device__ __align__(256) int   g_cursor[NNODES];
__device__ __align__(256) int   g_partial[NNODES];
__device__ __align__(256) int   g_bsum[NSCANBLK + 1];
__device__ __align__(256) int   g_colp[EMAX];

// ---------------- degree histogram ----------------
__global__ void k_deg(const int* __restrict__ row, int E, int* __restrict__ deg) {
    int i = blockIdx.x * blockDim.x + threadIdx.x;
    if (i < E) atomicAdd(&deg[row[i]], 1);   // no return use -> REDG
}

__global__ void k_dinv(const int* __restrict__ deg, float* __restrict__ dinv) {
    int i = blockIdx.x * blockDim.x + threadIdx.x;
    if (i < NNODES) {
        int d = deg[i];
        dinv[i] = (d > 0) ? rsqrtf((float)d) : 0.0f;
    }
}

// ---------------- exclusive scan of deg -> rowptr (3 kernels) ----------------
__global__ void k_scan1(const int* __restrict__ deg, int* __restrict__ partial,
                        int* __restrict__ bsum) {
    __shared__ int sm[SCANB];
    int i = blockIdx.x * SCANB + threadIdx.x;
    int v = (i < NNODES) ? deg[i] : 0;
    sm[threadIdx.x] = v;
    __syncthreads();
    #pragma unroll
    for (int off = 1; off < SCANB; off <<= 1) {
        int t = (threadIdx.x >= off) ? sm[threadIdx.x - off] : 0;
        __syncthreads();
        sm[threadIdx.x] += t;
        __syncthreads();
    }
    if (i < NNODES) partial[i] = sm[threadIdx.x];       // inclusive within block
    if (threadIdx.x == SCANB - 1) bsum[blockIdx.x] = sm[SCANB - 1];
}

__global__ void k_scan2(int* __restrict__ bsum, int nblk) {
    if (threadIdx.x == 0 && blockIdx.x == 0) {
        int run = 0;
        for (int b = 0; b < nblk; ++b) {
            int t = bsum[b];
            bsum[b] = run;
            run += t;
        }
        bsum[nblk] = run;  // == E
    }
}

__global__ void k_scan3(const int* __restrict__ deg, const int* __restrict__ partial,
                        const int* __restrict__ bsum,
                        int* __restrict__ rowptr, int* __restrict__ cursor, int E) {
    int i = blockIdx.x * blockDim.x + threadIdx.x;
    if (i < NNODES) {
        int ex = partial[i] - deg[i] + bsum[i / SCANB];
        rowptr[i] = ex;
        cursor[i] = ex;
    }
    if (i == 0) rowptr[NNODES] = E;
}

// ---------------- scatter edges into CSR ----------------
__global__ void k_scatter(const int* __restrict__ row, const int* __restrict__ col,
                          int* __restrict__ cursor, int* __restrict__ colp, int E) {
    int i = blockIdx.x * blockDim.x + threadIdx.x;
    if (i < E) {
        int pos = atomicAdd(&cursor[row[i]], 1);
        colp[pos] = col[i];
    }
}

// -------------- init: z = dinv * x, acc = x --------------
__global__ void k_initz(const float2* __restrict__ ue, const float2* __restrict__ ie,
                        const float* __restrict__ dinv,
                        float2* __restrict__ z, float2* __restrict__ acc) {
    int i = blockIdx.x * blockDim.x + threadIdx.x;
    const int total = NNODES * 32;          // float2 chunks
    if (i >= total) return;
    float2 v = (i < NUSERS * 32) ? ue[i] : ie[i - NUSERS * 32];
    acc[i] = v;
    float di = dinv[i >> 5];
    z[i] = make_float2(di * v.x, di * v.y);
}

// -------------- pull-based SpMM: warp per row, pure gather-sum --------------
__global__ void __launch_bounds__(256) k_pull(
        const int* __restrict__ rp, const int* __restrict__ colp,
        const float* __restrict__ dinv,
        const float2* __restrict__ zin, float2* __restrict__ zout,
        float2* __restrict__ acc) {
    int w = (blockIdx.x * blockDim.x + threadIdx.x) >> 5;
    int lane = threadIdx.x & 31;
    if (w >= NNODES) return;
    int beg = rp[w], end = rp[w + 1];
    float sx = 0.f, sy = 0.f;
    int e = beg;
    for (; e + 4 <= end; e += 4) {          // unroll x4 for MLP
        int c0 = colp[e + 0];
        int c1 = colp[e + 1];
        int c2 = colp[e + 2];
        int c3 = colp[e + 3];
        float2 a0 = zin[c0 * 32 + lane];
        float2 a1 = zin[c1 * 32 + lane];
        float2 a2 = zin[c2 * 32 + lane];
        float2 a3 = zin[c3 * 32 + lane];
        sx += a0.x + a1.x + a2.x + a3.x;
        sy += a0.y + a1.y + a2.y + a3.y;
    }
    for (; e < end; ++e) {
        int c = colp[e];
        float2 a = zin[c * 32 + lane];
        sx += a.x;
        sy += a.y;
    }
    float di = dinv[w];
    int o = w * 32 + lane;
    float2 ac = acc[o];
    ac.x = fmaf(di, sx, ac.x);
    ac.y = fmaf(di, sy, ac.y);
    acc[o] = ac;
    float d2 = di * di;
    zout[o] = make_float2(d2 * sx, d2 * sy);
}

// -------------- scores: one warp per (user, item) pair --------------
__global__ void k_score(const float* __restrict__ acc,
                        const int* __restrict__ uidx, const int* __restrict__ iidx,
                        float* __restrict__ out, int B) {
    int gtid = blockIdx.x * blockDim.x + threadIdx.x;
    int w = gtid >> 5;
    int lane = gtid & 31;
    if (w >= B) return;
    const float2* a = (const float2*)(acc + (size_t)uidx[w] * DIM);
    const float2* b = (const float2*)(acc + (size_t)(NUSERS + iidx[w]) * DIM);
    float2 av = a[lane];
    float2 bv = b[lane];
    float s = av.x * bv.x + av.y * bv.y;
    #pragma unroll
    for (int o = 16; o > 0; o >>= 1) s += __shfl_xor_sync(0xFFFFFFFFu, s, o);
    if (lane == 0) out[w] = s * 0.0625f;    // (1/4)^2 folded into the dot
}

extern "C" void kernel_launch(void* const* d_in, const int* in_sizes, int n_in,
                              void* d_out, int out_size) {
    const float* ue   = (const float*)d_in[0];
    const float* ie   = (const float*)d_in[1];
    const int*   row  = (const int*)d_in[2];
    const int*   col  = (const int*)d_in[3];
    const int*   uidx = (const int*)d_in[4];
    const int*   iidx = (const int*)d_in[5];
    const int E = in_sizes[2];
    const int B = in_sizes[4];

    float *z0, *z1, *acc, *dinv;
    int *deg, *rowptr, *cursor, *partial, *bsum, *colp;
    cudaGetSymbolAddress((void**)&z0,      g_z0);
    cudaGetSymbolAddress((void**)&z1,      g_z1);
    cudaGetSymbolAddress((void**)&acc,     g_acc);
    cudaGetSymbolAddress((void**)&deg,     g_deg);
    cudaGetSymbolAddress((void**)&dinv,    g_dinv);
    cudaGetSymbolAddress((void**)&rowptr,  g_rowptr);
    cudaGetSymbolAddress((void**)&cursor,  g_cursor);
    cudaGetSymbolAddress((void**)&partial, g_partial);
    cudaGetSymbolAddress((void**)&bsum,    g_bsum);
    cudaGetSymbolAddress((void**)&colp,    g_colp);

    const int TB = 256;

    // ---- CSR construction ----
    cudaMemsetAsync(deg, 0, NNODES * sizeof(int));
    k_deg<<<(E + TB - 1) / TB, TB>>>(row, E, deg);
    k_scan1<<<NSCANBLK, SCANB>>>(deg, partial, bsum);
    k_scan2<<<1, 32>>>(bsum, NSCANBLK);
    k_scan3<<<(NNODES + TB - 1) / TB, TB>>>(deg, partial, bsum, rowptr, cursor, E);
    k_scatter<<<(E + TB - 1) / TB, TB>>>(row, col, cursor, colp, E);
    k_dinv<<<(NNODES + TB - 1) / TB, TB>>>(deg, dinv);

    // ---- init z = dinv*x, acc = x ----
    k_initz<<<(NNODES * 32 + TB - 1) / TB, TB>>>((const float2*)ue, (const float2*)ie,
                                                 dinv, (float2*)z0, (float2*)acc);

    // ---- 3 pull layers, ping-pong z0 <-> z1, acc fused ----
    float* bufs[2] = { z0, z1 };
    const int pull_blocks = (NNODES * 32 + TB - 1) / TB;   // warp per row
    for (int l = 0; l < 3; ++l) {
        k_pull<<<pull_blocks, TB>>>(rowptr, colp, dinv,
                                    (const float2*)bufs[l & 1],
                                    (float2*)bufs[(l + 1) & 1],
                                    (float2*)acc);
    }

    // ---- scores ----
    k_score<<<(B * 32 + TB - 1) / TB, TB>>>(acc, uidx, iidx, (float*)d_out, B);
}

// round 3
// speedup vs baseline: 2.2974x; 1.0707x over previous
#include <cuda_runtime.h>
#include <cuda_fp16.h>
#include <cstdint>

#define NUSERS 100000
#define NITEMS 50000
#define NNODES 150000
#define DIM 64
#define EMAX 3200000
#define SCANB 1024
#define NSCANBLK ((NNODES + SCANB - 1) / SCANB)   // 147

// ---- scratch (device globals: allocation-free) ----
__device__ __align__(256) __half g_z0[NNODES * DIM];
__device__ __align__(256) __half g_z1[NNODES * DIM];
__device__ __align__(256) float  g_acc[NNODES * DIM];
__device__ __align__(256) int    g_deg[NNODES];
__device__ __align__(256) float  g_dinv[NNODES];
__device__ __align__(256) int    g_rowptr[NNODES + 1];
__device__ __align__(256) int    g_cursor[NNODES];
__device__ __align__(256) int    g_partial[NNODES];
__device__ __align__(256) int    g_bsum[NSCANBLK + 1];
__device__ __align__(256) int    g_colp[EMAX];

// ---------------- degree histogram ----------------
__global__ void k_deg(const int* __restrict__ row, int E, int* __restrict__ deg) {
    int i = blockIdx.x * blockDim.x + threadIdx.x;
    if (i < E) atomicAdd(&deg[row[i]], 1);   // no return use -> REDG
}

// ---------------- exclusive scan of deg -> rowptr ----------------
__global__ void k_scan1(const int* __restrict__ deg, int* __restrict__ partial,
                        int* __restrict__ bsum) {
    __shared__ int sm[SCANB];
    int i = blockIdx.x * SCANB + threadIdx.x;
    int v = (i < NNODES) ? deg[i] : 0;
    sm[threadIdx.x] = v;
    __syncthreads();
    #pragma unroll
    for (int off = 1; off < SCANB; off <<= 1) {
        int t = (threadIdx.x >= off) ? sm[threadIdx.x - off] : 0;
        __syncthreads();
        sm[threadIdx.x] += t;
        __syncthreads();
    }
    if (i < NNODES) partial[i] = sm[threadIdx.x];       // inclusive within block
    if (threadIdx.x == SCANB - 1) bsum[blockIdx.x] = sm[SCANB - 1];
}

__global__ void k_scan2(int* __restrict__ bsum, int nblk) {
    if (threadIdx.x == 0 && blockIdx.x == 0) {
        int run = 0;
        for (int b = 0; b < nblk; ++b) {
            int t = bsum[b];
            bsum[b] = run;
            run += t;
        }
        bsum[nblk] = run;  // == E
    }
}

// rowptr/cursor + dinv fused
__global__ void k_scan3(const int* __restrict__ deg, const int* __restrict__ partial,
                        const int* __restrict__ bsum,
                        int* __restrict__ rowptr, int* __restrict__ cursor,
                        float* __restrict__ dinv, int E) {
    int i = blockIdx.x * blockDim.x + threadIdx.x;
    if (i < NNODES) {
        int d = deg[i];
        int ex = partial[i] - d + bsum[i / SCANB];
        rowptr[i] = ex;
        cursor[i] = ex;
        dinv[i] = (d > 0) ? rsqrtf((float)d) : 0.0f;
    }
    if (i == 0) rowptr[NNODES] = E;
}

// ---------------- scatter edges into CSR ----------------
__global__ void k_scatter(const int* __restrict__ row, const int* __restrict__ col,
                          int* __restrict__ cursor, int* __restrict__ colp, int E) {
    int i = blockIdx.x * blockDim.x + threadIdx.x;
    if (i < E) {
        int pos = atomicAdd(&cursor[row[i]], 1);
        colp[pos] = col[i];
    }
}

// -------------- init: z = half(dinv * x), acc = x --------------
__global__ void k_initz(const float2* __restrict__ ue, const float2* __restrict__ ie,
                        const float* __restrict__ dinv,
                        __half2* __restrict__ z, float2* __restrict__ acc) {
    int i = blockIdx.x * blockDim.x + threadIdx.x;
    const int total = NNODES * 32;          // float2 / half2 chunks
    if (i >= total) return;
    float2 v = (i < NUSERS * 32) ? ue[i] : ie[i - NUSERS * 32];
    acc[i] = v;
    float di = dinv[i >> 5];
    z[i] = __floats2half2_rn(di * v.x, di * v.y);
}

// -------------- pull-based SpMM: warp per row, fp16 gathers, fp32 accum --------------
__global__ void __launch_bounds__(256) k_pull(
        const int* __restrict__ rp, const int* __restrict__ colp,
        const float* __restrict__ dinv,
        const __half2* __restrict__ zin, __half2* __restrict__ zout,
        float2* __restrict__ acc) {
    int w = (blockIdx.x * blockDim.x + threadIdx.x) >> 5;
    int lane = threadIdx.x & 31;
    if (w >= NNODES) return;
    int beg = rp[w], end = rp[w + 1];
    float sx = 0.f, sy = 0.f;
    int e = beg;
    for (; e + 4 <= end; e += 4) {          // unroll x4 for MLP
        int c0 = colp[e + 0];
        int c1 = colp[e + 1];
        int c2 = colp[e + 2];
        int c3 = colp[e + 3];
        float2 a0 = __half22float2(zin[c0 * 32 + lane]);
        float2 a1 = __half22float2(zin[c1 * 32 + lane]);
        float2 a2 = __half22float2(zin[c2 * 32 + lane]);
        float2 a3 = __half22float2(zin[c3 * 32 + lane]);
        sx += (a0.x + a1.x) + (a2.x + a3.x);
        sy += (a0.y + a1.y) + (a2.y + a3.y);
    }
    for (; e < end; ++e) {
        int c = colp[e];
        float2 a = __half22float2(zin[c * 32 + lane]);
        sx += a.x;
        sy += a.y;
    }
    float di = dinv[w];
    int o = w * 32 + lane;
    float2 ac = acc[o];
    ac.x = fmaf(di, sx, ac.x);
    ac.y = fmaf(di, sy, ac.y);
    acc[o] = ac;
    float d2 = di * di;
    zout[o] = __floats2half2_rn(d2 * sx, d2 * sy);
}

// -------------- scores: one warp per (user, item) pair --------------
__global__ void k_score(const float* __restrict__ acc,
                        const int* __restrict__ uidx, const int* __restrict__ iidx,
                        float* __restrict__ out, int B) {
    int gtid = blockIdx.x * blockDim.x + threadIdx.x;
    int w = gtid >> 5;
    int lane = gtid & 31;
    if (w >= B) return;
    const float2* a = (const float2*)(acc + (size_t)uidx[w] * DIM);
    const float2* b = (const float2*)(acc + (size_t)(NUSERS + iidx[w]) * DIM);
    float2 av = a[lane];
    float2 bv = b[lane];
    float s = av.x * bv.x + av.y * bv.y;
    #pragma unroll
    for (int o = 16; o > 0; o >>= 1) s += __shfl_xor_sync(0xFFFFFFFFu, s, o);
    if (lane == 0) out[w] = s * 0.0625f;    // (1/4)^2 folded into the dot
}

extern "C" void kernel_launch(void* const* d_in, const int* in_sizes, int n_in,
                              void* d_out, int out_size) {
    const float* ue   = (const float*)d_in[0];
    const float* ie   = (const float*)d_in[1];
    const int*   row  = (const int*)d_in[2];
    const int*   col  = (const int*)d_in[3];
    const int*   uidx = (const int*)d_in[4];
    const int*   iidx = (const int*)d_in[5];
    const int E = in_sizes[2];
    const int B = in_sizes[4];

    __half *z0, *z1;
    float *acc, *dinv;
    int *deg, *rowptr, *cursor, *partial, *bsum, *colp;
    cudaGetSymbolAddress((void**)&z0,      g_z0);
    cudaGetSymbolAddress((void**)&z1,      g_z1);
    cudaGetSymbolAddress((void**)&acc,     g_acc);
    cudaGetSymbolAddress((void**)&deg,     g_deg);
    cudaGetSymbolAddress((void**)&dinv,    g_dinv);
    cudaGetSymbolAddress((void**)&rowptr,  g_rowptr);
    cudaGetSymbolAddress((void**)&cursor,  g_cursor);
    cudaGetSymbolAddress((void**)&partial, g_partial);
    cudaGetSymbolAddress((void**)&bsum,    g_bsum);
    cudaGetSymbolAddress((void**)&colp,    g_colp);

    const int TB = 256;

    // ---- CSR construction ----
    cudaMemsetAsync(deg, 0, NNODES * sizeof(int));
    k_deg<<<(E + TB - 1) / TB, TB>>>(row, E, deg);
    k_scan1<<<NSCANBLK, SCANB>>>(deg, partial, bsum);
    k_scan2<<<1, 32>>>(bsum, NSCANBLK);
    k_scan3<<<(NNODES + TB - 1) / TB, TB>>>(deg, partial, bsum, rowptr, cursor, dinv, E);
    k_scatter<<<(E + TB - 1) / TB, TB>>>(row, col, cursor, colp, E);

    // ---- init z = half(dinv*x), acc = x ----
    k_initz<<<(NNODES * 32 + TB - 1) / TB, TB>>>((const float2*)ue, (const float2*)ie,
                                                 dinv, (__half2*)z0, (float2*)acc);

    // ---- 3 pull layers, ping-pong z0 <-> z1, acc fused ----
    __half* bufs[2] = { z0, z1 };
    const int pull_blocks = (NNODES * 32 + TB - 1) / TB;   // warp per row
    for (int l = 0; l < 3; ++l) {
        k_pull<<<pull_blocks, TB>>>(rowptr, colp, dinv,
                                    (const __half2*)bufs[l & 1],
                                    (__half2*)bufs[(l + 1) & 1],
                                    (float2*)acc);
    }

    // ---- scores ----
    k_score<<<(B * 32 + TB - 1) / TB, TB>>>(acc, uidx, iidx, (float*)d_out, B);
}

// round 4
// speedup vs baseline: 2.4415x; 1.0627x over previous
#include <cuda_runtime.h>
#include <cuda_fp16.h>
#include <cstdint>

#define NUSERS 100000
#define NITEMS 50000
#define NNODES 150000
#define DIM 64
#define EMAX 3200000
#define SCANB 1024
#define NSCANBLK ((NNODES + SCANB - 1) / SCANB)   // 147

// ---- scratch (device globals: allocation-free) ----
__device__ __align__(256) __half g_z0[NNODES * DIM];
__device__ __align__(256) __half g_z1[NNODES * DIM];
__device__ __align__(256) float  g_acc[NNODES * DIM];
__device__ __align__(256) int    g_deg[NNODES];
__device__ __align__(256) float  g_dinv[NNODES];
__device__ __align__(256) int    g_rowptr[NNODES + 1];
__device__ __align__(256) int    g_cursor[NNODES];
__device__ __align__(256) int    g_partial[NNODES];
__device__ __align__(256) int    g_bsum[NSCANBLK + 1];
__device__ __align__(256) int    g_colp[EMAX];

// ---------------- degree histogram ----------------
__global__ void k_deg(const int* __restrict__ row, int E, int* __restrict__ deg) {
    int i = blockIdx.x * blockDim.x + threadIdx.x;
    if (i < E) atomicAdd(&deg[row[i]], 1);   // no return use -> REDG
}

// ---------------- exclusive scan of deg -> rowptr ----------------
__global__ void k_scan1(const int* __restrict__ deg, int* __restrict__ partial,
                        int* __restrict__ bsum) {
    __shared__ int sm[SCANB];
    int i = blockIdx.x * SCANB + threadIdx.x;
    int v = (i < NNODES) ? deg[i] : 0;
    sm[threadIdx.x] = v;
    __syncthreads();
    #pragma unroll
    for (int off = 1; off < SCANB; off <<= 1) {
        int t = (threadIdx.x >= off) ? sm[threadIdx.x - off] : 0;
        __syncthreads();
        sm[threadIdx.x] += t;
        __syncthreads();
    }
    if (i < NNODES) partial[i] = sm[threadIdx.x];       // inclusive within block
    if (threadIdx.x == SCANB - 1) bsum[blockIdx.x] = sm[SCANB - 1];
}

// parallel scan of the 147 block sums (one block, shared memory)
__global__ void k_scan2(int* __restrict__ bsum, int nblk) {
    __shared__ int sm[256];
    int t = threadIdx.x;
    int v = (t < nblk) ? bsum[t] : 0;
    sm[t] = v;
    __syncthreads();
    #pragma unroll
    for (int off = 1; off < 256; off <<= 1) {
        int u = (t >= off) ? sm[t - off] : 0;
        __syncthreads();
        sm[t] += u;
        __syncthreads();
    }
    // exclusive result
    if (t < nblk) bsum[t] = sm[t] - v;
    if (t == nblk) { /* nothing */ }
    if (t == 255) bsum[nblk] = sm[nblk - 1];  // total == E (sm holds inclusive)
}

// rowptr/cursor + dinv fused
__global__ void k_scan3(const int* __restrict__ deg, const int* __restrict__ partial,
                        const int* __restrict__ bsum,
                        int* __restrict__ rowptr, int* __restrict__ cursor,
                        float* __restrict__ dinv, int E) {
    int i = blockIdx.x * blockDim.x + threadIdx.x;
    if (i < NNODES) {
        int d = deg[i];
        int ex = partial[i] - d + bsum[i / SCANB];
        rowptr[i] = ex;
        cursor[i] = ex;
        dinv[i] = (d > 0) ? rsqrtf((float)d) : 0.0f;
    }
    if (i == 0) rowptr[NNODES] = E;
}

// ---------------- scatter edges into CSR ----------------
__global__ void k_scatter(const int* __restrict__ row, const int* __restrict__ col,
                          int* __restrict__ cursor, int* __restrict__ colp, int E) {
    int i = blockIdx.x * blockDim.x + threadIdx.x;
    if (i < E) {
        int pos = atomicAdd(&cursor[row[i]], 1);
        colp[pos] = col[i];
    }
}

// -------------- init: z = half(dinv * x), acc = x --------------
__global__ void k_initz(const float2* __restrict__ ue, const float2* __restrict__ ie,
                        const float* __restrict__ dinv,
                        __half2* __restrict__ z, float2* __restrict__ acc) {
    int i = blockIdx.x * blockDim.x + threadIdx.x;
    const int total = NNODES * 32;          // float2 / half2 chunks
    if (i >= total) return;
    float2 v = (i < NUSERS * 32) ? ue[i] : ie[i - NUSERS * 32];
    acc[i] = v;
    float di = dinv[i >> 5];
    z[i] = __floats2half2_rn(di * v.x, di * v.y);
}

// -------------- pull-based SpMM: warp per row, fp16 gathers, fp32 accum --------------
__global__ void __launch_bounds__(256) k_pull(
        const int* __restrict__ rp, const int* __restrict__ colp,
        const float* __restrict__ dinv,
        const __half2* __restrict__ zin, __half2* __restrict__ zout,
        float2* __restrict__ acc) {
    int w = (blockIdx.x * blockDim.x + threadIdx.x) >> 5;
    int lane = threadIdx.x & 31;
    if (w >= NNODES) return;
    int beg = rp[w], end = rp[w + 1];
    float sx = 0.f, sy = 0.f;
    int e = beg;
    for (; e + 8 <= end; e += 8) {          // unroll x8 for MLP
        int c0 = colp[e + 0];
        int c1 = colp[e + 1];
        int c2 = colp[e + 2];
        int c3 = colp[e + 3];
        int c4 = colp[e + 4];
        int c5 = colp[e + 5];
        int c6 = colp[e + 6];
        int c7 = colp[e + 7];
        float2 a0 = __half22float2(zin[c0 * 32 + lane]);
        float2 a1 = __half22float2(zin[c1 * 32 + lane]);
        float2 a2 = __half22float2(zin[c2 * 32 + lane]);
        float2 a3 = __half22float2(zin[c3 * 32 + lane]);
        float2 a4 = __half22float2(zin[c4 * 32 + lane]);
        float2 a5 = __half22float2(zin[c5 * 32 + lane]);
        float2 a6 = __half22float2(zin[c6 * 32 + lane]);
        float2 a7 = __half22float2(zin[c7 * 32 + lane]);
        sx += ((a0.x + a1.x) + (a2.x + a3.x)) + ((a4.x + a5.x) + (a6.x + a7.x));
        sy += ((a0.y + a1.y) + (a2.y + a3.y)) + ((a4.y + a5.y) + (a6.y + a7.y));
    }
    for (; e < end; ++e) {
        int c = colp[e];
        float2 a = __half22float2(zin[c * 32 + lane]);
        sx += a.x;
        sy += a.y;
    }
    float di = dinv[w];
    int o = w * 32 + lane;
    float2 ac = acc[o];
    ac.x = fmaf(di, sx, ac.x);
    ac.y = fmaf(di, sy, ac.y);
    acc[o] = ac;
    float d2 = di * di;
    zout[o] = __floats2half2_rn(d2 * sx, d2 * sy);
}

// -------------- scores: one warp per (user, item) pair --------------
__global__ void k_score(const float* __restrict__ acc,
                        const int* __restrict__ uidx, const int* __restrict__ iidx,
                        float* __restrict__ out, int B) {
    int gtid = blockIdx.x * blockDim.x + threadIdx.x;
    int w = gtid >> 5;
    int lane = gtid & 31;
    if (w >= B) return;
    const float2* a = (const float2*)(acc + (size_t)uidx[w] * DIM);
    const float2* b = (const float2*)(acc + (size_t)(NUSERS + iidx[w]) * DIM);
    float2 av = a[lane];
    float2 bv = b[lane];
    float s = av.x * bv.x + av.y * bv.y;
    #pragma unroll
    for (int o = 16; o > 0; o >>= 1) s += __shfl_xor_sync(0xFFFFFFFFu, s, o);
    if (lane == 0) out[w] = s * 0.0625f;    // (1/4)^2 folded into the dot
}

extern "C" void kernel_launch(void* const* d_in, const int* in_sizes, int n_in,
                              void* d_out, int out_size) {
    const float* ue   = (const float*)d_in[0];
    const float* ie   = (const float*)d_in[1];
    const int*   row  = (const int*)d_in[2];
    const int*   col  = (const int*)d_in[3];
    const int*   uidx = (const int*)d_in[4];
    const int*   iidx = (const int*)d_in[5];
    const int E = in_sizes[2];
    const int B = in_sizes[4];

    __half *z0, *z1;
    float *acc, *dinv;
    int *deg, *rowptr, *cursor, *partial, *bsum, *colp;
    cudaGetSymbolAddress((void**)&z0,      g_z0);
    cudaGetSymbolAddress((void**)&z1,      g_z1);
    cudaGetSymbolAddress((void**)&acc,     g_acc);
    cudaGetSymbolAddress((void**)&deg,     g_deg);
    cudaGetSymbolAddress((void**)&dinv,    g_dinv);
    cudaGetSymbolAddress((void**)&rowptr,  g_rowptr);
    cudaGetSymbolAddress((void**)&cursor,  g_cursor);
    cudaGetSymbolAddress((void**)&partial, g_partial);
    cudaGetSymbolAddress((void**)&bsum,    g_bsum);
    cudaGetSymbolAddress((void**)&colp,    g_colp);

    const int TB = 256;

    // ---- CSR construction ----
    cudaMemsetAsync(deg, 0, NNODES * sizeof(int));
    k_deg<<<(E + TB - 1) / TB, TB>>>(row, E, deg);
    k_scan1<<<NSCANBLK, SCANB>>>(deg, partial, bsum);
    k_scan2<<<1, 256>>>(bsum, NSCANBLK);
    k_scan3<<<(NNODES + TB - 1) / TB, TB>>>(deg, partial, bsum, rowptr, cursor, dinv, E);
    k_scatter<<<(E + TB - 1) / TB, TB>>>(row, col, cursor, colp, E);

    // ---- init z = half(dinv*x), acc = x ----
    k_initz<<<(NNODES * 32 + TB - 1) / TB, TB>>>((const float2*)ue, (const float2*)ie,
                                                 dinv, (__half2*)z0, (float2*)acc);

    // ---- 3 pull layers, ping-pong z0 <-> z1, acc fused ----
    __half* bufs[2] = { z0, z1 };
    const int pull_blocks = (NNODES * 32 + TB - 1) / TB;   // warp per row
    for (int l = 0; l < 3; ++l) {
        k_pull<<<pull_blocks, TB>>>(rowptr, colp, dinv,
                                    (const __half2*)bufs[l & 1],
                                    (__half2*)bufs[(l + 1) & 1],
                                    (float2*)acc);
    }

    // ---- scores ----
    k_score<<<(B * 32 + TB - 1) / TB, TB>>>(acc, uidx, iidx, (float*)d_out, B);
}

// round 5
// speedup vs baseline: 2.7485x; 1.1257x over previous
#include <cuda_runtime.h>
#include <cuda_fp16.h>
#include <cstdint>

#define NUSERS 100000
#define NITEMS 50000
#define NNODES 150000
#define DIM 64
#define EMAX 3200000
#define SCANB 1024
#define NSCANBLK ((NNODES + SCANB - 1) / SCANB)   // 147

// ---- scratch (device globals: allocation-free) ----
__device__ __align__(256) __half g_z0[NNODES * DIM];
__device__ __align__(256) __half g_z1[NNODES * DIM];
__device__ __align__(256) __half g_z2[NNODES * DIM];
__device__ __align__(256) __half g_z3[NNODES * DIM];
__device__ __align__(256) int    g_deg[NNODES];
__device__ __align__(256) float  g_dinv[NNODES];
__device__ __align__(256) int    g_rowptr[NNODES + 1];
__device__ __align__(256) int    g_cursor[NNODES];
__device__ __align__(256) int    g_partial[NNODES];
__device__ __align__(256) int    g_bsum[NSCANBLK + 1];
__device__ __align__(256) int    g_colp[EMAX];

// ---------------- degree histogram ----------------
__global__ void k_deg(const int* __restrict__ row, int E, int* __restrict__ deg) {
    int i = blockIdx.x * blockDim.x + threadIdx.x;
    if (i < E) atomicAdd(&deg[row[i]], 1);   // no return use -> REDG
}

// ---------------- exclusive scan of deg -> rowptr ----------------
__global__ void k_scan1(const int* __restrict__ deg, int* __restrict__ partial,
                        int* __restrict__ bsum) {
    __shared__ int sm[SCANB];
    int i = blockIdx.x * SCANB + threadIdx.x;
    int v = (i < NNODES) ? deg[i] : 0;
    sm[threadIdx.x] = v;
    __syncthreads();
    #pragma unroll
    for (int off = 1; off < SCANB; off <<= 1) {
        int t = (threadIdx.x >= off) ? sm[threadIdx.x - off] : 0;
        __syncthreads();
        sm[threadIdx.x] += t;
        __syncthreads();
    }
    if (i < NNODES) partial[i] = sm[threadIdx.x];       // inclusive within block
    if (threadIdx.x == SCANB - 1) bsum[blockIdx.x] = sm[SCANB - 1];
}

// parallel scan of the 147 block sums (one block, shared memory)
__global__ void k_scan2(int* __restrict__ bsum, int nblk) {
    __shared__ int sm[256];
    int t = threadIdx.x;
    int v = (t < nblk) ? bsum[t] : 0;
    sm[t] = v;
    __syncthreads();
    #pragma unroll
    for (int off = 1; off < 256; off <<= 1) {
        int u = (t >= off) ? sm[t - off] : 0;
        __syncthreads();
        sm[t] += u;
        __syncthreads();
    }
    if (t < nblk) bsum[t] = sm[t] - v;       // exclusive
    if (t == 255) bsum[nblk] = sm[nblk - 1]; // total == E
}

// rowptr/cursor + dinv fused
__global__ void k_scan3(const int* __restrict__ deg, const int* __restrict__ partial,
                        const int* __restrict__ bsum,
                        int* __restrict__ rowptr, int* __restrict__ cursor,
                        float* __restrict__ dinv, int E) {
    int i = blockIdx.x * blockDim.x + threadIdx.x;
    if (i < NNODES) {
        int d = deg[i];
        int ex = partial[i] - d + bsum[i / SCANB];
        rowptr[i] = ex;
        cursor[i] = ex;
        dinv[i] = (d > 0) ? rsqrtf((float)d) : 0.0f;
    }
    if (i == 0) rowptr[NNODES] = E;
}

// ---------------- scatter edges into CSR ----------------
__global__ void k_scatter(const int* __restrict__ row, const int* __restrict__ col,
                          int* __restrict__ cursor, int* __restrict__ colp, int E) {
    int i = blockIdx.x * blockDim.x + threadIdx.x;
    if (i < E) {
        int pos = atomicAdd(&cursor[row[i]], 1);
        colp[pos] = col[i];
    }
}

// -------------- init: z0 = half(dinv * x) --------------
__global__ void k_initz(const float2* __restrict__ ue, const float2* __restrict__ ie,
                        const float* __restrict__ dinv,
                        __half2* __restrict__ z) {
    int i = blockIdx.x * blockDim.x + threadIdx.x;
    const int total = NNODES * 32;          // half2 chunks
    if (i >= total) return;
    float2 v = (i < NUSERS * 32) ? ue[i] : ie[i - NUSERS * 32];
    float di = dinv[i >> 5];
    z[i] = __floats2half2_rn(di * v.x, di * v.y);
}

// -------------- pull-based SpMM: warp per row, fp16 gathers, fp32 accum --------------
__global__ void __launch_bounds__(256) k_pull(
        const int* __restrict__ rp, const int* __restrict__ colp,
        const float* __restrict__ dinv,
        const __half2* __restrict__ zin, __half2* __restrict__ zout) {
    int w = (blockIdx.x * blockDim.x + threadIdx.x) >> 5;
    int lane = threadIdx.x & 31;
    if (w >= NNODES) return;
    int beg = rp[w], end = rp[w + 1];
    float sx = 0.f, sy = 0.f;
    int e = beg;
    for (; e + 8 <= end; e += 8) {          // unroll x8 for MLP
        int c0 = colp[e + 0];
        int c1 = colp[e + 1];
        int c2 = colp[e + 2];
        int c3 = colp[e + 3];
        int c4 = colp[e + 4];
        int c5 = colp[e + 5];
        int c6 = colp[e + 6];
        int c7 = colp[e + 7];
        float2 a0 = __half22float2(zin[c0 * 32 + lane]);
        float2 a1 = __half22float2(zin[c1 * 32 + lane]);
        float2 a2 = __half22float2(zin[c2 * 32 + lane]);
        float2 a3 = __half22float2(zin[c3 * 32 + lane]);
        float2 a4 = __half22float2(zin[c4 * 32 + lane]);
        float2 a5 = __half22float2(zin[c5 * 32 + lane]);
        float2 a6 = __half22float2(zin[c6 * 32 + lane]);
        float2 a7 = __half22float2(zin[c7 * 32 + lane]);
        sx += ((a0.x + a1.x) + (a2.x + a3.x)) + ((a4.x + a5.x) + (a6.x + a7.x));
        sy += ((a0.y + a1.y) + (a2.y + a3.y)) + ((a4.y + a5.y) + (a6.y + a7.y));
    }
    for (; e < end; ++e) {
        int c = colp[e];
        float2 a = __half22float2(zin[c * 32 + lane]);
        sx += a.x;
        sy += a.y;
    }
    float di = dinv[w];
    float d2 = di * di;
    zout[w * 32 + lane] = __floats2half2_rn(d2 * sx, d2 * sy);
}

// -------------- scores: final = x0 + sqrt(deg)*(z1+z2+z3) at sampled nodes --------------
__global__ void k_score(const float2* __restrict__ ue, const float2* __restrict__ ie,
                        const __half2* __restrict__ z1, const __half2* __restrict__ z2,
                        const __half2* __restrict__ z3, const int* __restrict__ deg,
                        const int* __restrict__ uidx, const int* __restrict__ iidx,
                        float* __restrict__ out, int B) {
    int gtid = blockIdx.x * blockDim.x + threadIdx.x;
    int w = gtid >> 5;
    int lane = gtid & 31;
    if (w >= B) return;
    int un = uidx[w];
    int in = NUSERS + iidx[w];
    float su = sqrtf((float)deg[un]);
    float si = sqrtf((float)deg[in]);

    int uo = un * 32 + lane;
    int io = in * 32 + lane;

    float2 fu = ue[uo];
    float2 zu1 = __half22float2(z1[uo]);
    float2 zu2 = __half22float2(z2[uo]);
    float2 zu3 = __half22float2(z3[uo]);
    fu.x = fmaf(su, (zu1.x + zu2.x) + zu3.x, fu.x);
    fu.y = fmaf(su, (zu1.y + zu2.y) + zu3.y, fu.y);

    float2 fi = ie[iidx[w] * 32 + lane];
    float2 zi1 = __half22float2(z1[io]);
    float2 zi2 = __half22float2(z2[io]);
    float2 zi3 = __half22float2(z3[io]);
    fi.x = fmaf(si, (zi1.x + zi2.x) + zi3.x, fi.x);
    fi.y = fmaf(si, (zi1.y + zi2.y) + zi3.y, fi.y);

    float s = fu.x * fi.x + fu.y * fi.y;
    #pragma unroll
    for (int o = 16; o > 0; o >>= 1) s += __shfl_xor_sync(0xFFFFFFFFu, s, o);
    if (lane == 0) out[w] = s * 0.0625f;    // (1/4)^2 folded into the dot
}

extern "C" void kernel_launch(void* const* d_in, const int* in_sizes, int n_in,
                              void* d_out, int out_size) {
    const float* ue   = (const float*)d_in[0];
    const float* ie   = (const float*)d_in[1];
    const int*   row  = (const int*)d_in[2];
    const int*   col  = (const int*)d_in[3];
    const int*   uidx = (const int*)d_in[4];
    const int*   iidx = (const int*)d_in[5];
    const int E = in_sizes[2];
    const int B = in_sizes[4];

    __half *z0, *z1, *z2, *z3;
    float *dinv;
    int *deg, *rowptr, *cursor, *partial, *bsum, *colp;
    cudaGetSymbolAddress((void**)&z0,      g_z0);
    cudaGetSymbolAddress((void**)&z1,      g_z1);
    cudaGetSymbolAddress((void**)&z2,      g_z2);
    cudaGetSymbolAddress((void**)&z3,      g_z3);
    cudaGetSymbolAddress((void**)&deg,     g_deg);
    cudaGetSymbolAddress((void**)&dinv,    g_dinv);
    cudaGetSymbolAddress((void**)&rowptr,  g_rowptr);
    cudaGetSymbolAddress((void**)&cursor,  g_cursor);
    cudaGetSymbolAddress((void**)&partial, g_partial);
    cudaGetSymbolAddress((void**)&bsum,    g_bsum);
    cudaGetSymbolAddress((void**)&colp,    g_colp);

    const int TB = 256;

    // ---- CSR construction ----
    cudaMemsetAsync(deg, 0, NNODES * sizeof(int));
    k_deg<<<(E + TB - 1) / TB, TB>>>(row, E, deg);
    k_scan1<<<NSCANBLK, SCANB>>>(deg, partial, bsum);
    k_scan2<<<1, 256>>>(bsum, NSCANBLK);
    k_scan3<<<(NNODES + TB - 1) / TB, TB>>>(deg, partial, bsum, rowptr, cursor, dinv, E);
    k_scatter<<<(E + TB - 1) / TB, TB>>>(row, col, cursor, colp, E);

    // ---- init z0 = half(dinv*x) ----
    k_initz<<<(NNODES * 32 + TB - 1) / TB, TB>>>((const float2*)ue, (const float2*)ie,
                                                 dinv, (__half2*)z0);

    // ---- 3 pull layers, distinct output buffers (no acc array) ----
    __half* zs[4] = { z0, z1, z2, z3 };
    const int pull_blocks = (NNODES * 32 + TB - 1) / TB;   // warp per row
    for (int l = 0; l < 3; ++l) {
        k_pull<<<pull_blocks, TB>>>(rowptr, colp, dinv,
                                    (const __half2*)zs[l],
                                    (__half2*)zs[l + 1]);
    }

    // ---- scores ----
    k_score<<<(B * 32 + TB - 1) / TB, TB>>>((const float2*)ue, (const float2*)ie,
                                            (const __half2*)z1, (const __half2*)z2,
                                            (const __half2*)z3, deg,
                                            uidx, iidx, (float*)d_out, B);
}